// round 1
// baseline (speedup 1.0000x reference)
#include <cuda_runtime.h>
#include <math.h>

#define NW 10
#define NL 4
#define DIM 1024
#define NSAMP 4096

// Scratch: split real/imag planes for X and Y states (16 MB each).
__device__ float g_Xr[NSAMP * DIM];
__device__ float g_Xi[NSAMP * DIM];
__device__ float g_Yr[NSAMP * DIM];
__device__ float g_Yi[NSAMP * DIM];

// Composite permutation of one CNOT ladder, traced backwards:
// sigma(b) = source index that ends up at b after CNOT(0,1),CNOT(1,2),...,CNOT(8,9),CNOT(9,0).
// Wire i lives at bit position (9 - i) (axis 0 = most significant).
__device__ __forceinline__ int sigma_perm(int b) {
    int s = b;
    // innermost (applied last in circuit): CNOT(c=9, t=0)
    s ^= ((s >> 0) & 1) << 9;
#pragma unroll
    for (int c = 8; c >= 0; --c) {
        // CNOT(c, c+1): control at bit (9-c), target at bit (8-c)
        s ^= ((s >> (9 - c)) & 1) << (8 - c);
    }
    return s;
}

__global__ void state_kernel(const float* __restrict__ ang,
                             const float* __restrict__ params,
                             int which) {
    float* outr = which ? g_Yr : g_Xr;
    float* outi = which ? g_Yi : g_Xi;
    const int sample = blockIdx.x;
    __shared__ float sc[NW], ss[NW], sp[NL * NW];
    const int tid = threadIdx.x;
    if (tid < NW) {
        float h = 0.5f * ang[sample * NW + tid];
        sc[tid] = cosf(h);
        ss[tid] = sinf(h);
    }
    if (tid < NL * NW) sp[tid] = params[tid];
    __syncthreads();

    for (int b = tid; b < DIM; b += blockDim.x) {
        int cur = b;
        float phase = 0.f;
#pragma unroll
        for (int l = NL - 1; l >= 0; --l) {
            cur = sigma_perm(cur);
#pragma unroll
            for (int i = 0; i < NW; ++i) {
                phase += (((cur >> (9 - i)) & 1) ? 0.5f : -0.5f) * sp[l * NW + i];
            }
        }
        float amp = 1.f;
#pragma unroll
        for (int i = 0; i < NW; ++i)
            amp *= (((cur >> (9 - i)) & 1) ? ss[i] : sc[i]);
        float sphi, cphi;
        sincosf(phase, &sphi, &cphi);
        outr[sample * DIM + b] = amp * cphi;
        outi[sample * DIM + b] = amp * sphi;
    }
}

// Complex GEMM: C[i][j] = |sum_k X[i,k] * conj(Y[j,k])|^2
// Re = xr*yr + xi*yi ; Im = xi*yr - xr*yi
#define BM 64
#define BN 64
#define BK 16

__global__ void __launch_bounds__(256, 2)
gemm_kernel(float* __restrict__ C) {
    __shared__ __align__(16) float As_r[BK][BM];
    __shared__ __align__(16) float As_i[BK][BM];
    __shared__ __align__(16) float Bs_r[BK][BN];
    __shared__ __align__(16) float Bs_i[BK][BN];

    const int tid = threadIdx.x;
    const int bm = blockIdx.y * BM;
    const int bn = blockIdx.x * BN;
    const int lrow = tid >> 2;          // 0..63
    const int lcol = (tid & 3) << 2;    // 0,4,8,12
    const int ty = tid >> 4;            // 0..15
    const int tx = tid & 15;            // 0..15

    float cr[4][4] = {};
    float ci[4][4] = {};

    const float* Agr = g_Xr + (size_t)(bm + lrow) * DIM + lcol;
    const float* Agi = g_Xi + (size_t)(bm + lrow) * DIM + lcol;
    const float* Bgr = g_Yr + (size_t)(bn + lrow) * DIM + lcol;
    const float* Bgi = g_Yi + (size_t)(bn + lrow) * DIM + lcol;

    for (int k0 = 0; k0 < DIM; k0 += BK) {
        float4 va_r = *(const float4*)(Agr + k0);
        float4 va_i = *(const float4*)(Agi + k0);
        float4 vb_r = *(const float4*)(Bgr + k0);
        float4 vb_i = *(const float4*)(Bgi + k0);
        __syncthreads();
        As_r[lcol + 0][lrow] = va_r.x; As_r[lcol + 1][lrow] = va_r.y;
        As_r[lcol + 2][lrow] = va_r.z; As_r[lcol + 3][lrow] = va_r.w;
        As_i[lcol + 0][lrow] = va_i.x; As_i[lcol + 1][lrow] = va_i.y;
        As_i[lcol + 2][lrow] = va_i.z; As_i[lcol + 3][lrow] = va_i.w;
        Bs_r[lcol + 0][lrow] = vb_r.x; Bs_r[lcol + 1][lrow] = vb_r.y;
        Bs_r[lcol + 2][lrow] = vb_r.z; Bs_r[lcol + 3][lrow] = vb_r.w;
        Bs_i[lcol + 0][lrow] = vb_i.x; Bs_i[lcol + 1][lrow] = vb_i.y;
        Bs_i[lcol + 2][lrow] = vb_i.z; Bs_i[lcol + 3][lrow] = vb_i.w;
        __syncthreads();
#pragma unroll
        for (int k = 0; k < BK; ++k) {
            float4 ar4 = *(const float4*)(&As_r[k][ty << 2]);
            float4 ai4 = *(const float4*)(&As_i[k][ty << 2]);
            float4 br4 = *(const float4*)(&Bs_r[k][tx << 2]);
            float4 bi4 = *(const float4*)(&Bs_i[k][tx << 2]);
            float arr[4] = {ar4.x, ar4.y, ar4.z, ar4.w};
            float aii[4] = {ai4.x, ai4.y, ai4.z, ai4.w};
            float brr[4] = {br4.x, br4.y, br4.z, br4.w};
            float bii[4] = {bi4.x, bi4.y, bi4.z, bi4.w};
#pragma unroll
            for (int m = 0; m < 4; ++m) {
#pragma unroll
                for (int n = 0; n < 4; ++n) {
                    cr[m][n] += arr[m] * brr[n] + aii[m] * bii[n];
                    ci[m][n] += aii[m] * brr[n] - arr[m] * bii[n];
                }
            }
        }
    }

#pragma unroll
    for (int m = 0; m < 4; ++m) {
        int row = bm + (ty << 2) + m;
        float* Cp = C + (size_t)row * NSAMP + bn + (tx << 2);
        float4 v;
        v.x = cr[m][0] * cr[m][0] + ci[m][0] * ci[m][0];
        v.y = cr[m][1] * cr[m][1] + ci[m][1] * ci[m][1];
        v.z = cr[m][2] * cr[m][2] + ci[m][2] * ci[m][2];
        v.w = cr[m][3] * cr[m][3] + ci[m][3] * ci[m][3];
        *(float4*)Cp = v;
    }
}

extern "C" void kernel_launch(void* const* d_in, const int* in_sizes, int n_in,
                              void* d_out, int out_size) {
    const float* X = (const float*)d_in[0];      // (4096, 10)
    const float* Y = (const float*)d_in[1];      // (4096, 10)
    const float* P = (const float*)d_in[2];      // (4, 10)
    float* out = (float*)d_out;                  // (4096, 4096)

    state_kernel<<<NSAMP, 256>>>(X, P, 0);
    state_kernel<<<NSAMP, 256>>>(Y, P, 1);

    dim3 grid(NSAMP / BN, NSAMP / BM);
    gemm_kernel<<<grid, 256>>>(out);
}

// round 4
// speedup vs baseline: 2.6334x; 2.6334x over previous
#include <cuda_runtime.h>
#include <cuda_bf16.h>
#include <math.h>
#include <stdint.h>

#define NW 10
#define NL 4
#define DIM 1024
#define NSAMP 4096
#define KEXP 6144            // 3x split-expanded K ( [hi|hi|lo] x [hi|lo|hi] )
#define NB 8192              // Re-variant rows + Im-variant rows

// ---------------- device scratch (only ever referenced from DEVICE code) ----------------
__device__ __nv_bfloat16 g_A[(size_t)NSAMP * KEXP];   // 50 MB
__device__ __nv_bfloat16 g_B[(size_t)NB * KEXP];      // 100 MB
__device__ float g_C[(size_t)NSAMP * NB];             // 128 MB

// ---------------- circuit math ----------------
// sigma(b) = source index mapped to b by one CNOT ladder (traced backwards).
__device__ __forceinline__ int sigma_perm(int b) {
    int s = b;
    s ^= ((s >> 0) & 1) << 9;            // CNOT(9,0) applied last
#pragma unroll
    for (int c = 8; c >= 0; --c) {
        s ^= ((s >> (9 - c)) & 1) << (8 - c);   // CNOT(c, c+1)
    }
    return s;
}

__device__ __forceinline__ void split_bf16(float x, __nv_bfloat16& h, __nv_bfloat16& l) {
    h = __float2bfloat16_rn(x);
    l = __float2bfloat16_rn(x - __bfloat162float(h));
}

// which = 0 -> write A (X states); which = 1 -> write B (Y states, both variants)
__global__ void prep_kernel(const float* __restrict__ ang,
                            const float* __restrict__ params,
                            int which) {
    const int sample = blockIdx.x;
    __shared__ float sc[NW], ss[NW], sp[NL * NW];
    const int tid = threadIdx.x;
    if (tid < NW) {
        float h = 0.5f * ang[sample * NW + tid];
        sc[tid] = cosf(h);
        ss[tid] = sinf(h);
    }
    if (tid < NL * NW) sp[tid] = params[tid];
    __syncthreads();

    for (int t = 0; t < DIM / 256; ++t) {
        int b = tid + t * 256;
        int cur = b;
        float phase = 0.f;
#pragma unroll
        for (int l = NL - 1; l >= 0; --l) {
            cur = sigma_perm(cur);
#pragma unroll
            for (int i = 0; i < NW; ++i)
                phase += (((cur >> (9 - i)) & 1) ? 0.5f : -0.5f) * sp[l * NW + i];
        }
        float amp = 1.f;
#pragma unroll
        for (int i = 0; i < NW; ++i)
            amp *= (((cur >> (9 - i)) & 1) ? ss[i] : sc[i]);
        float sphi, cphi;
        sincosf(phase, &sphi, &cphi);
        float re = amp * cphi;
        float im = amp * sphi;

        if (which == 0) {
            // A row: [hi(re,im) | hi(re,im) | lo(re,im)]
            __nv_bfloat16 hr, lr, hi_, li;
            split_bf16(re, hr, lr);
            split_bf16(im, hi_, li);
            __nv_bfloat16* Ar = g_A + (size_t)sample * KEXP;
            Ar[b]          = hr;  Ar[1024 + b] = hi_;
            Ar[2048 + b]   = hr;  Ar[3072 + b] = hi_;
            Ar[4096 + b]   = lr;  Ar[5120 + b] = li;
        } else {
            // B rows: j -> (u,v)=(yr,yi)  [Re];  j+4096 -> (u,v)=(-yi,yr)  [Im]
            // layout per row: [hi(u,v) | lo(u,v) | hi(u,v)]
#pragma unroll
            for (int variant = 0; variant < 2; ++variant) {
                float u = variant ? -im : re;
                float v = variant ? re : im;
                __nv_bfloat16 hu, lu, hv, lv;
                split_bf16(u, hu, lu);
                split_bf16(v, hv, lv);
                __nv_bfloat16* Br = g_B + (size_t)(sample + variant * NSAMP) * KEXP;
                Br[b]        = hu;  Br[1024 + b] = hv;
                Br[2048 + b] = lu;  Br[3072 + b] = lv;
                Br[4096 + b] = hu;  Br[5120 + b] = hv;
            }
        }
    }
}

// ---------------- bf16 tensor-core GEMM ----------------
// g_C[i][j] = sum_k g_A[i][k] * g_B[j][k]   (both K-major -> mma row.col)
#define BM 128
#define BN 128
#define KC 32
#define STAGES 2
#define PAD 40   // 32 bf16 + 16B pad -> 80B rows, conflict-free ldmatrix

__device__ __forceinline__ void cp16(__nv_bfloat16* sdst, const __nv_bfloat16* gsrc) {
    uint32_t s = (uint32_t)__cvta_generic_to_shared(sdst);
    asm volatile("cp.async.cg.shared.global [%0], [%1], 16;\n" :: "r"(s), "l"(gsrc));
}
__device__ __forceinline__ void cp_commit() {
    asm volatile("cp.async.commit_group;\n");
}
__device__ __forceinline__ void ldsm_x4(uint32_t& r0, uint32_t& r1, uint32_t& r2, uint32_t& r3,
                                        const __nv_bfloat16* p) {
    uint32_t s = (uint32_t)__cvta_generic_to_shared(p);
    asm volatile("ldmatrix.sync.aligned.m8n8.x4.shared.b16 {%0,%1,%2,%3}, [%4];\n"
                 : "=r"(r0), "=r"(r1), "=r"(r2), "=r"(r3) : "r"(s));
}
__device__ __forceinline__ void mma16816(float& d0, float& d1, float& d2, float& d3,
                                         uint32_t a0, uint32_t a1, uint32_t a2, uint32_t a3,
                                         uint32_t b0, uint32_t b1) {
    asm volatile("mma.sync.aligned.m16n8k16.row.col.f32.bf16.bf16.f32 "
                 "{%0,%1,%2,%3},{%4,%5,%6,%7},{%8,%9},{%0,%1,%2,%3};\n"
                 : "+f"(d0), "+f"(d1), "+f"(d2), "+f"(d3)
                 : "r"(a0), "r"(a1), "r"(a2), "r"(a3), "r"(b0), "r"(b1));
}

// Static shared: 2 stages * (128+128) rows * 40 bf16 = 40960 bytes (< 48 KB)
__global__ void __launch_bounds__(256, 2)
bmma_kernel() {
    __shared__ __align__(16) __nv_bfloat16 As[STAGES * BM * PAD];
    __shared__ __align__(16) __nv_bfloat16 Bs[STAGES * BN * PAD];

    const int tid = threadIdx.x;
    const int bm = blockIdx.y * BM;
    const int bn = blockIdx.x * BN;
    const int warp = tid >> 5;
    const int lane = tid & 31;
    const int m_w = (warp >> 2) * 64;   // 0 or 64
    const int n_w = (warp & 3) * 32;    // 0,32,64,96

    // per-thread cp.async offsets (2 chunks each for A and B)
    const int r0 = tid >> 2,         c0 = (tid & 3) << 3;
    const int r1 = (tid + 256) >> 2, c1 = c0;

    float acc[4][4][4];
#pragma unroll
    for (int i = 0; i < 4; ++i)
#pragma unroll
        for (int j = 0; j < 4; ++j)
#pragma unroll
            for (int k = 0; k < 4; ++k) acc[i][j][k] = 0.f;

    const __nv_bfloat16* gA = g_A + (size_t)bm * KEXP;
    const __nv_bfloat16* gB = g_B + (size_t)bn * KEXP;

#define LOAD_STAGE(s, kt) do {                                                     \
        int k0 = (kt) * KC;                                                        \
        cp16(As + ((s) * BM + r0) * PAD + c0, gA + (size_t)r0 * KEXP + k0 + c0);   \
        cp16(As + ((s) * BM + r1) * PAD + c1, gA + (size_t)r1 * KEXP + k0 + c1);   \
        cp16(Bs + ((s) * BN + r0) * PAD + c0, gB + (size_t)r0 * KEXP + k0 + c0);   \
        cp16(Bs + ((s) * BN + r1) * PAD + c1, gB + (size_t)r1 * KEXP + k0 + c1);   \
        cp_commit();                                                               \
    } while (0)

    const int NT = KEXP / KC;   // 192
    LOAD_STAGE(0, 0);

    // ldmatrix per-thread row/col components
    const int a_row = lane & 15;
    const int a_col = (lane >> 4) << 3;
    const int b_row = ((lane >> 4) << 3) + (lane & 7);
    const int b_col = ((lane >> 3) & 1) << 3;

    for (int kt = 0; kt < NT; ++kt) {
        const int cur = kt & 1;
        if (kt + 1 < NT) {
            LOAD_STAGE(cur ^ 1, kt + 1);
            asm volatile("cp.async.wait_group 1;\n");   // stage kt complete
        } else {
            asm volatile("cp.async.wait_group 0;\n");   // drain everything
        }
        __syncthreads();

        const __nv_bfloat16* Asb = As + cur * BM * PAD;
        const __nv_bfloat16* Bsb = Bs + cur * BN * PAD;
#pragma unroll
        for (int ks = 0; ks < 2; ++ks) {
            int k16 = ks * 16;
            uint32_t a[4][4], b[2][4];
#pragma unroll
            for (int mt = 0; mt < 4; ++mt)
                ldsm_x4(a[mt][0], a[mt][1], a[mt][2], a[mt][3],
                        Asb + (m_w + mt * 16 + a_row) * PAD + k16 + a_col);
#pragma unroll
            for (int nt2 = 0; nt2 < 2; ++nt2)
                ldsm_x4(b[nt2][0], b[nt2][1], b[nt2][2], b[nt2][3],
                        Bsb + (n_w + nt2 * 16 + b_row) * PAD + k16 + b_col);
#pragma unroll
            for (int mt = 0; mt < 4; ++mt)
#pragma unroll
                for (int nt = 0; nt < 4; ++nt) {
                    int nt2 = nt >> 1, h = nt & 1;
                    mma16816(acc[mt][nt][0], acc[mt][nt][1], acc[mt][nt][2], acc[mt][nt][3],
                             a[mt][0], a[mt][1], a[mt][2], a[mt][3],
                             b[nt2][2 * h], b[nt2][2 * h + 1]);
                }
        }
        __syncthreads();   // protect stage `cur` before it is overwritten next iter
    }

    // epilogue: write g_C
#pragma unroll
    for (int mt = 0; mt < 4; ++mt) {
#pragma unroll
        for (int nt = 0; nt < 4; ++nt) {
            int m0 = bm + m_w + mt * 16 + (lane >> 2);
            int n0 = bn + n_w + nt * 8 + ((lane & 3) << 1);
            float2 v0 = make_float2(acc[mt][nt][0], acc[mt][nt][1]);
            float2 v1 = make_float2(acc[mt][nt][2], acc[mt][nt][3]);
            *(float2*)(g_C + (size_t)m0 * NB + n0) = v0;
            *(float2*)(g_C + (size_t)(m0 + 8) * NB + n0) = v1;
        }
    }
#undef LOAD_STAGE
}

// ---------------- |.|^2 epilogue ----------------
__global__ void epi_kernel(float* __restrict__ out) {
    int idx = blockIdx.x * 256 + threadIdx.x;          // over NSAMP * 1024
    int i = idx >> 10;
    int j4 = (idx & 1023) << 2;
    const float4 re = *(const float4*)(g_C + (size_t)i * NB + j4);
    const float4 im = *(const float4*)(g_C + (size_t)i * NB + 4096 + j4);
    float4 o;
    o.x = re.x * re.x + im.x * im.x;
    o.y = re.y * re.y + im.y * im.y;
    o.z = re.z * re.z + im.z * im.z;
    o.w = re.w * re.w + im.w * im.w;
    *(float4*)(out + (size_t)i * NSAMP + j4) = o;
}

extern "C" void kernel_launch(void* const* d_in, const int* in_sizes, int n_in,
                              void* d_out, int out_size) {
    const float* X = (const float*)d_in[0];      // (4096, 10)
    const float* Y = (const float*)d_in[1];      // (4096, 10)
    const float* P = (const float*)d_in[2];      // (4, 10)
    float* out = (float*)d_out;                  // (4096, 4096)

    prep_kernel<<<NSAMP, 256>>>(X, P, 0);
    prep_kernel<<<NSAMP, 256>>>(Y, P, 1);

    dim3 grid(NB / BN, NSAMP / BM);
    bmma_kernel<<<grid, 256>>>();

    epi_kernel<<<NSAMP * DIM / 256, 256>>>(out);
}

// round 6
// speedup vs baseline: 3.1067x; 1.1798x over previous
#include <cuda_runtime.h>
#include <cuda_bf16.h>
#include <math.h>
#include <stdint.h>

#define NW 10
#define NL 4
#define DIM 1024
#define NSAMP 4096
#define KEXP 6144            // 3x split-expanded K ( [hi|hi|lo] x [hi|lo|hi] )
#define NBROW 8192           // interleaved: row 2j = Re-variant, 2j+1 = Im-variant

// ---------------- device scratch (device-code references ONLY) ----------------
__device__ __nv_bfloat16 g_A[(size_t)NSAMP * KEXP];   // 50 MB
__device__ __nv_bfloat16 g_B[(size_t)NBROW * KEXP];   // 100 MB
__device__ int   g_perm[DIM];
__device__ float g_cph[DIM];
__device__ float g_sph[DIM];

// ---------------- circuit tables ----------------
__device__ __forceinline__ int sigma_perm(int b) {
    int s = b;
    s ^= ((s >> 0) & 1) << 9;            // CNOT(9,0) applied last
#pragma unroll
    for (int c = 8; c >= 0; --c)
        s ^= ((s >> (9 - c)) & 1) << (8 - c);   // CNOT(c, c+1)
    return s;
}

__global__ void table_kernel(const float* __restrict__ params) {
    int b = threadIdx.x;
    int cur = b;
    float phase = 0.f;
#pragma unroll
    for (int l = NL - 1; l >= 0; --l) {
        cur = sigma_perm(cur);
#pragma unroll
        for (int i = 0; i < NW; ++i)
            phase += (((cur >> (9 - i)) & 1) ? 0.5f : -0.5f) * params[l * NW + i];
    }
    g_perm[b] = cur;
    float s, c;
    sincosf(phase, &s, &c);
    g_sph[b] = s;
    g_cph[b] = c;
}

__device__ __forceinline__ void split_bf16(float x, __nv_bfloat16& h, __nv_bfloat16& l) {
    h = __float2bfloat16_rn(x);
    l = __float2bfloat16_rn(x - __bfloat162float(h));
}

// grid (NSAMP, 2): y==0 -> A from X; y==1 -> B (interleaved Re/Im rows) from Y
__global__ void prep_kernel(const float* __restrict__ X, const float* __restrict__ Y) {
    const int which = blockIdx.y;
    const float* ang = which ? Y : X;
    const int sample = blockIdx.x;
    const int b = threadIdx.x;            // 1024 threads
    __shared__ float sc[NW], ss[NW];
    if (b < NW) {
        float h = 0.5f * ang[sample * NW + b];
        sc[b] = cosf(h);
        ss[b] = sinf(h);
    }
    __syncthreads();

    const int cur = g_perm[b];
    float amp = 1.f;
#pragma unroll
    for (int i = 0; i < NW; ++i)
        amp *= (((cur >> (9 - i)) & 1) ? ss[i] : sc[i]);
    const float re = amp * g_cph[b];
    const float im = amp * g_sph[b];

    __nv_bfloat16 hr, lr, hi_, li;
    split_bf16(re, hr, lr);
    split_bf16(im, hi_, li);

    if (which == 0) {
        // A row: [hi(re,im) | hi(re,im) | lo(re,im)]
        __nv_bfloat16* Ar = g_A + (size_t)sample * KEXP;
        Ar[b]        = hr;  Ar[1024 + b] = hi_;
        Ar[2048 + b] = hr;  Ar[3072 + b] = hi_;
        Ar[4096 + b] = lr;  Ar[5120 + b] = li;
    } else {
        // Row 2j   (Re): (u,v) = ( re, im);  layout [hi(u,v) | lo(u,v) | hi(u,v)]
        // Row 2j+1 (Im): (u,v) = (-im, re)   (negated splits are exact)
        __nv_bfloat16* Br0 = g_B + (size_t)(2 * sample) * KEXP;
        Br0[b]        = hr;  Br0[1024 + b] = hi_;
        Br0[2048 + b] = lr;  Br0[3072 + b] = li;
        Br0[4096 + b] = hr;  Br0[5120 + b] = hi_;
        __nv_bfloat16 nh = __hneg(hi_), nl = __hneg(li);
        __nv_bfloat16* Br1 = g_B + (size_t)(2 * sample + 1) * KEXP;
        Br1[b]        = nh;  Br1[1024 + b] = hr;
        Br1[2048 + b] = nl;  Br1[3072 + b] = lr;
        Br1[4096 + b] = nh;  Br1[5120 + b] = hr;
    }
}

// ---------------- bf16 mma.sync GEMM + fused |.|^2 epilogue ----------------
// D[i][n] = sum_k A[i][k] * B[n][k]; out[i][j] = D[i][2j]^2 + D[i][2j+1]^2
#define BM 128
#define BNR 128              // B rows per CTA (= 64 outputs)
#define KC 64                // K per pipeline stage
#define NT (KEXP / KC)       // 96
#define STG 3
#define PAD 72               // 64 bf16 + 8 pad -> 144B rows (conflict-free, checked)
#define STG_ELEMS (256 * PAD)   // A rows 0..127, B rows 128..255

__device__ __forceinline__ void cp16(uint32_t sdst, const void* gsrc) {
    asm volatile("cp.async.cg.shared.global [%0], [%1], 16;\n" :: "r"(sdst), "l"(gsrc));
}
__device__ __forceinline__ void ldsm_x4(uint32_t& r0, uint32_t& r1, uint32_t& r2, uint32_t& r3,
                                        const __nv_bfloat16* p) {
    uint32_t s = (uint32_t)__cvta_generic_to_shared(p);
    asm volatile("ldmatrix.sync.aligned.m8n8.x4.shared.b16 {%0,%1,%2,%3}, [%4];\n"
                 : "=r"(r0), "=r"(r1), "=r"(r2), "=r"(r3) : "r"(s));
}
__device__ __forceinline__ void mma16816(float& d0, float& d1, float& d2, float& d3,
                                         uint32_t a0, uint32_t a1, uint32_t a2, uint32_t a3,
                                         uint32_t b0, uint32_t b1) {
    asm volatile("mma.sync.aligned.m16n8k16.row.col.f32.bf16.bf16.f32 "
                 "{%0,%1,%2,%3},{%4,%5,%6,%7},{%8,%9},{%0,%1,%2,%3};\n"
                 : "+f"(d0), "+f"(d1), "+f"(d2), "+f"(d3)
                 : "r"(a0), "r"(a1), "r"(a2), "r"(a3), "r"(b0), "r"(b1));
}

__global__ void __launch_bounds__(256, 2)
qk_gemm(float* __restrict__ out) {
    extern __shared__ __nv_bfloat16 sm[];
    const uint32_t smb = (uint32_t)__cvta_generic_to_shared(sm);

    const int tid = threadIdx.x;
    const int warp = tid >> 5;
    const int lane = tid & 31;
    const int bm = blockIdx.y * BM;
    const int bn = blockIdx.x * BNR;
    const int m_w = (warp >> 2) * 64;   // 0 or 64
    const int n_w = (warp & 3) * 32;    // 0,32,64,96

    float acc[4][4][4];
#pragma unroll
    for (int i = 0; i < 4; ++i)
#pragma unroll
        for (int j = 0; j < 4; ++j)
#pragma unroll
            for (int k = 0; k < 4; ++k) acc[i][j][k] = 0.f;

#define FILL(stage, kt) do {                                                        \
        const uint32_t sb = smb + (uint32_t)(stage) * STG_ELEMS * 2;                \
        const int k0 = (kt) * KC;                                                   \
        _Pragma("unroll")                                                           \
        for (int q = 0; q < 4; ++q) {                                               \
            int c = tid + q * 256;                                                  \
            int row = c >> 3, col8 = (c & 7) << 3;                                  \
            cp16(sb + (uint32_t)(row * PAD + col8) * 2,                             \
                 g_A + (size_t)(bm + row) * KEXP + k0 + col8);                      \
            cp16(sb + (uint32_t)((128 + row) * PAD + col8) * 2,                     \
                 g_B + (size_t)(bn + row) * KEXP + k0 + col8);                      \
        }                                                                           \
        asm volatile("cp.async.commit_group;\n");                                   \
    } while (0)

    FILL(0, 0);
    FILL(1, 1);

    const int a_row = lane & 15;
    const int a_col = (lane >> 4) << 3;
    const int b_row = ((lane >> 4) << 3) + (lane & 7);
    const int b_col = ((lane >> 3) & 1) << 3;

    for (int kt = 0; kt < NT; ++kt) {
        if (kt + 2 < NT) {
            FILL((kt + 2) % 3, kt + 2);
            asm volatile("cp.async.wait_group 2;\n" ::: "memory");
        } else if (kt + 1 < NT) {
            asm volatile("cp.async.wait_group 1;\n" ::: "memory");
        } else {
            asm volatile("cp.async.wait_group 0;\n" ::: "memory");
        }
        __syncthreads();

        const __nv_bfloat16* Asb = sm + (kt % 3) * STG_ELEMS;
        const __nv_bfloat16* Bsb = Asb + 128 * PAD;
#pragma unroll
        for (int ks = 0; ks < 4; ++ks) {
            const int k16 = ks * 16;
            uint32_t a[4][4], b[2][4];
#pragma unroll
            for (int mt = 0; mt < 4; ++mt)
                ldsm_x4(a[mt][0], a[mt][1], a[mt][2], a[mt][3],
                        Asb + (m_w + mt * 16 + a_row) * PAD + k16 + a_col);
#pragma unroll
            for (int nt2 = 0; nt2 < 2; ++nt2)
                ldsm_x4(b[nt2][0], b[nt2][1], b[nt2][2], b[nt2][3],
                        Bsb + (n_w + nt2 * 16 + b_row) * PAD + k16 + b_col);
#pragma unroll
            for (int mt = 0; mt < 4; ++mt)
#pragma unroll
                for (int nt = 0; nt < 4; ++nt) {
                    int nt2 = nt >> 1, h = nt & 1;
                    mma16816(acc[mt][nt][0], acc[mt][nt][1], acc[mt][nt][2], acc[mt][nt][3],
                             a[mt][0], a[mt][1], a[mt][2], a[mt][3],
                             b[nt2][2 * h], b[nt2][2 * h + 1]);
                }
        }
        __syncthreads();
    }
#undef FILL

    // fused epilogue: thread's (c0,c1)/(c2,c3) = (Re,Im) of one output each
#pragma unroll
    for (int mt = 0; mt < 4; ++mt) {
#pragma unroll
        for (int nt = 0; nt < 4; ++nt) {
            int row0 = bm + m_w + mt * 16 + (lane >> 2);
            int j = (bn >> 1) + (n_w >> 1) + nt * 4 + (lane & 3);
            float v0 = acc[mt][nt][0] * acc[mt][nt][0] + acc[mt][nt][1] * acc[mt][nt][1];
            float v1 = acc[mt][nt][2] * acc[mt][nt][2] + acc[mt][nt][3] * acc[mt][nt][3];
            out[(size_t)row0 * NSAMP + j] = v0;
            out[(size_t)(row0 + 8) * NSAMP + j] = v1;
        }
    }
}

extern "C" void kernel_launch(void* const* d_in, const int* in_sizes, int n_in,
                              void* d_out, int out_size) {
    const float* X = (const float*)d_in[0];      // (4096, 10)
    const float* Y = (const float*)d_in[1];      // (4096, 10)
    const float* P = (const float*)d_in[2];      // (4, 10)
    float* out = (float*)d_out;                  // (4096, 4096)

    const int smem_bytes = STG * STG_ELEMS * (int)sizeof(__nv_bfloat16);  // 110592
    cudaFuncSetAttribute(qk_gemm, cudaFuncAttributeMaxDynamicSharedMemorySize, smem_bytes);

    table_kernel<<<1, DIM>>>(P);
    prep_kernel<<<dim3(NSAMP, 2), DIM>>>(X, Y);

    dim3 grid(NBROW / BNR, NSAMP / BM);   // (64, 32)
    qk_gemm<<<grid, 256, smem_bytes>>>(out);
}

// round 7
// speedup vs baseline: 3.4324x; 1.1048x over previous
#include <cuda_runtime.h>
#include <cuda_bf16.h>
#include <math.h>
#include <stdint.h>

#define NW 10
#define NL 4
#define DIM 1024
#define NSAMP 4096
#define KEXP 6144            // 3x split-expanded K ( [hi|hi|lo] x [hi|lo|hi] )
#define NBROW 8192           // interleaved: row 2j = Re-variant, 2j+1 = Im-variant

// ---------------- device scratch (device-code references ONLY) ----------------
__device__ __nv_bfloat16 g_A[(size_t)NSAMP * KEXP];   // 50 MB
__device__ __nv_bfloat16 g_B[(size_t)NBROW * KEXP];   // 100 MB
__device__ int   g_perm[DIM];
__device__ float g_cph[DIM];
__device__ float g_sph[DIM];

// ---------------- circuit tables ----------------
__device__ __forceinline__ int sigma_perm(int b) {
    int s = b;
    s ^= ((s >> 0) & 1) << 9;            // CNOT(9,0) applied last
#pragma unroll
    for (int c = 8; c >= 0; --c)
        s ^= ((s >> (9 - c)) & 1) << (8 - c);   // CNOT(c, c+1)
    return s;
}

__global__ void table_kernel(const float* __restrict__ params) {
    int b = threadIdx.x;
    int cur = b;
    float phase = 0.f;
#pragma unroll
    for (int l = NL - 1; l >= 0; --l) {
        cur = sigma_perm(cur);
#pragma unroll
        for (int i = 0; i < NW; ++i)
            phase += (((cur >> (9 - i)) & 1) ? 0.5f : -0.5f) * params[l * NW + i];
    }
    g_perm[b] = cur;
    float s, c;
    sincosf(phase, &s, &c);
    g_sph[b] = s;
    g_cph[b] = c;
}

__device__ __forceinline__ void split_bf16(float x, __nv_bfloat16& h, __nv_bfloat16& l) {
    h = __float2bfloat16_rn(x);
    l = __float2bfloat16_rn(x - __bfloat162float(h));
}

// grid (NSAMP, 2): y==0 -> A from X; y==1 -> B (interleaved Re/Im rows) from Y
__global__ void prep_kernel(const float* __restrict__ X, const float* __restrict__ Y) {
    const int which = blockIdx.y;
    const float* ang = which ? Y : X;
    const int sample = blockIdx.x;
    const int b = threadIdx.x;            // 1024 threads
    __shared__ float sc[NW], ss[NW];
    if (b < NW) {
        float h = 0.5f * ang[sample * NW + b];
        sc[b] = cosf(h);
        ss[b] = sinf(h);
    }
    __syncthreads();

    const int cur = g_perm[b];
    float amp = 1.f;
#pragma unroll
    for (int i = 0; i < NW; ++i)
        amp *= (((cur >> (9 - i)) & 1) ? ss[i] : sc[i]);
    const float re = amp * g_cph[b];
    const float im = amp * g_sph[b];

    __nv_bfloat16 hr, lr, hi_, li;
    split_bf16(re, hr, lr);
    split_bf16(im, hi_, li);

    if (which == 0) {
        // A row: [hi(re,im) | hi(re,im) | lo(re,im)]
        __nv_bfloat16* Ar = g_A + (size_t)sample * KEXP;
        Ar[b]        = hr;  Ar[1024 + b] = hi_;
        Ar[2048 + b] = hr;  Ar[3072 + b] = hi_;
        Ar[4096 + b] = lr;  Ar[5120 + b] = li;
    } else {
        // Row 2j   (Re): (u,v) = ( re, im);  layout [hi(u,v) | lo(u,v) | hi(u,v)]
        // Row 2j+1 (Im): (u,v) = (-im, re)   (negated splits are exact)
        __nv_bfloat16* Br0 = g_B + (size_t)(2 * sample) * KEXP;
        Br0[b]        = hr;  Br0[1024 + b] = hi_;
        Br0[2048 + b] = lr;  Br0[3072 + b] = li;
        Br0[4096 + b] = hr;  Br0[5120 + b] = hi_;
        __nv_bfloat16 nh = __hneg(hi_), nl = __hneg(li);
        __nv_bfloat16* Br1 = g_B + (size_t)(2 * sample + 1) * KEXP;
        Br1[b]        = nh;  Br1[1024 + b] = hr;
        Br1[2048 + b] = nl;  Br1[3072 + b] = lr;
        Br1[4096 + b] = nh;  Br1[5120 + b] = hr;
    }
}

// ---------------- bf16 mma.sync GEMM + fused |.|^2 epilogue ----------------
// D[i][n] = sum_k A[i][k] * B[n][k]; out[i][j] = D[i][2j]^2 + D[i][2j+1]^2
#define BM 128
#define BNR 256              // B rows per CTA (= 128 outputs)
#define KC 64                // K per pipeline stage
#define NT (KEXP / KC)       // 96
#define STG 4
#define PAD 72               // 64 bf16 + 8 pad -> 144B rows, conflict-free
#define STG_ROWS (BM + BNR)            // 384 rows per stage (A then B)
#define STG_ELEMS (STG_ROWS * PAD)     // bf16 elems per stage

__device__ __forceinline__ void cp16(uint32_t sdst, const void* gsrc) {
    asm volatile("cp.async.cg.shared.global [%0], [%1], 16;\n" :: "r"(sdst), "l"(gsrc));
}
__device__ __forceinline__ void ldsm_x4(uint32_t& r0, uint32_t& r1, uint32_t& r2, uint32_t& r3,
                                        const __nv_bfloat16* p) {
    uint32_t s = (uint32_t)__cvta_generic_to_shared(p);
    asm volatile("ldmatrix.sync.aligned.m8n8.x4.shared.b16 {%0,%1,%2,%3}, [%4];\n"
                 : "=r"(r0), "=r"(r1), "=r"(r2), "=r"(r3) : "r"(s));
}
__device__ __forceinline__ void mma16816(float& d0, float& d1, float& d2, float& d3,
                                         uint32_t a0, uint32_t a1, uint32_t a2, uint32_t a3,
                                         uint32_t b0, uint32_t b1) {
    asm volatile("mma.sync.aligned.m16n8k16.row.col.f32.bf16.bf16.f32 "
                 "{%0,%1,%2,%3},{%4,%5,%6,%7},{%8,%9},{%0,%1,%2,%3};\n"
                 : "+f"(d0), "+f"(d1), "+f"(d2), "+f"(d3)
                 : "r"(a0), "r"(a1), "r"(a2), "r"(a3), "r"(b0), "r"(b1));
}

__global__ void __launch_bounds__(256)
qk_gemm(float* __restrict__ out) {
    extern __shared__ __nv_bfloat16 sm[];
    const uint32_t smb = (uint32_t)__cvta_generic_to_shared(sm);

    const int tid = threadIdx.x;
    const int warp = tid >> 5;
    const int lane = tid & 31;
    const int bm = blockIdx.y * BM;
    const int bn = blockIdx.x * BNR;
    const int m_w = (warp >> 2) * 64;   // 0 or 64
    const int n_w = (warp & 3) * 64;    // 0,64,128,192 (B rows)

    float acc[4][8][4];
#pragma unroll
    for (int i = 0; i < 4; ++i)
#pragma unroll
        for (int j = 0; j < 8; ++j)
#pragma unroll
            for (int k = 0; k < 4; ++k) acc[i][j][k] = 0.f;

    // 3072 16B-chunks per stage / 256 threads = 12 per thread
#define FILL(stage, kt) do {                                                        \
        const uint32_t sb = smb + (uint32_t)(stage) * STG_ELEMS * 2;                \
        const int k0 = (kt) * KC;                                                   \
        _Pragma("unroll")                                                           \
        for (int q = 0; q < 12; ++q) {                                              \
            int c = tid + q * 256;                                                  \
            int row = c >> 3, col8 = (c & 7) << 3;                                  \
            const void* src = (row < BM)                                            \
                ? (const void*)(g_A + (size_t)(bm + row) * KEXP + k0 + col8)        \
                : (const void*)(g_B + (size_t)(bn + row - BM) * KEXP + k0 + col8);  \
            cp16(sb + (uint32_t)(row * PAD + col8) * 2, src);                       \
        }                                                                           \
        asm volatile("cp.async.commit_group;\n");                                   \
    } while (0)

    FILL(0, 0);
    FILL(1, 1);
    FILL(2, 2);

    const int a_row = lane & 15;
    const int a_col = (lane >> 4) << 3;
    const int b_row = ((lane >> 4) << 3) + (lane & 7);
    const int b_col = ((lane >> 3) & 1) << 3;

    for (int kt = 0; kt < NT; ++kt) {
        if (kt < NT - 2) {
            asm volatile("cp.async.wait_group 2;\n" ::: "memory");
        } else if (kt == NT - 2) {
            asm volatile("cp.async.wait_group 1;\n" ::: "memory");
        } else {
            asm volatile("cp.async.wait_group 0;\n" ::: "memory");
        }
        __syncthreads();

        const __nv_bfloat16* Asb = sm + (kt & 3) * STG_ELEMS;
        const __nv_bfloat16* Bsb = Asb + BM * PAD;
#pragma unroll
        for (int ks = 0; ks < 4; ++ks) {
            const int k16 = ks * 16;
            uint32_t a[4][4], b[4][4];
#pragma unroll
            for (int mt = 0; mt < 4; ++mt)
                ldsm_x4(a[mt][0], a[mt][1], a[mt][2], a[mt][3],
                        Asb + (m_w + mt * 16 + a_row) * PAD + k16 + a_col);
#pragma unroll
            for (int nt2 = 0; nt2 < 4; ++nt2)
                ldsm_x4(b[nt2][0], b[nt2][1], b[nt2][2], b[nt2][3],
                        Bsb + (n_w + nt2 * 16 + b_row) * PAD + k16 + b_col);
#pragma unroll
            for (int mt = 0; mt < 4; ++mt)
#pragma unroll
                for (int nt = 0; nt < 8; ++nt) {
                    int nt2 = nt >> 1, h = nt & 1;
                    mma16816(acc[mt][nt][0], acc[mt][nt][1], acc[mt][nt][2], acc[mt][nt][3],
                             a[mt][0], a[mt][1], a[mt][2], a[mt][3],
                             b[nt2][2 * h], b[nt2][2 * h + 1]);
                }
        }
        // FILL for kt+3 goes into stage (kt+3)&3, which last held kt-1:
        // every warp passed this iteration's __syncthreads, so kt-1 is fully consumed.
        if (kt + 3 < NT) FILL((kt + 3) & 3, kt + 3);
    }
#undef FILL

    // fused epilogue: (c0,c1) and (c2,c3) are (Re,Im) pairs of single outputs
#pragma unroll
    for (int mt = 0; mt < 4; ++mt) {
#pragma unroll
        for (int nt = 0; nt < 8; ++nt) {
            int row0 = bm + m_w + mt * 16 + (lane >> 2);
            int j = (bn >> 1) + (n_w >> 1) + nt * 4 + (lane & 3);
            float v0 = acc[mt][nt][0] * acc[mt][nt][0] + acc[mt][nt][1] * acc[mt][nt][1];
            float v1 = acc[mt][nt][2] * acc[mt][nt][2] + acc[mt][nt][3] * acc[mt][nt][3];
            out[(size_t)row0 * NSAMP + j] = v0;
            out[(size_t)(row0 + 8) * NSAMP + j] = v1;
        }
    }
}

extern "C" void kernel_launch(void* const* d_in, const int* in_sizes, int n_in,
                              void* d_out, int out_size) {
    const float* X = (const float*)d_in[0];      // (4096, 10)
    const float* Y = (const float*)d_in[1];      // (4096, 10)
    const float* P = (const float*)d_in[2];      // (4, 10)
    float* out = (float*)d_out;                  // (4096, 4096)

    const int smem_bytes = STG * STG_ELEMS * (int)sizeof(__nv_bfloat16);  // 221184
    cudaFuncSetAttribute(qk_gemm, cudaFuncAttributeMaxDynamicSharedMemorySize, smem_bytes);

    table_kernel<<<1, DIM>>>(P);
    prep_kernel<<<dim3(NSAMP, 2), DIM>>>(X, Y);

    dim3 grid(NBROW / BNR, NSAMP / BM);   // (32, 32)
    qk_gemm<<<grid, 256, smem_bytes>>>(out);
}

// round 8
// speedup vs baseline: 83.4850x; 24.3229x over previous
#include <cuda_runtime.h>
#include <math.h>

#define NW 10
#define NSAMP 4096
#define TILE 128

// out[x, y] = prod_i cos^2((X[x,i] - Y[y,i]) / 2)
//
// Derivation: both state batches pass through the SAME unitary (RZ layers +
// CNOT ladders with shared params), so <psi_x|psi_y> = <RY(x)0|RY(y)0>
// (unitary invariance). The product-state overlap factorizes per qubit:
//   <q(x_i)|q(y_i)> = cos(x_i/2)cos(y_i/2) + sin(x_i/2)sin(y_i/2)
//                   = cos((x_i - y_i)/2)   (real)
// This matches the verified table-based decomposition of rounds 4-7, where the
// phase/permutation tables depended only on the basis index, never the sample.

__global__ void __launch_bounds__(256)
qk_kernel(const float* __restrict__ X, const float* __restrict__ Y,
          float* __restrict__ out) {
    // wire-major, float4-aligned rows
    __shared__ __align__(16) float scx[NW][TILE], ssx[NW][TILE];
    __shared__ __align__(16) float scy[NW][TILE], ssy[NW][TILE];

    const int tid = threadIdx.x;
    const int bm = blockIdx.y * TILE;   // X rows
    const int bn = blockIdx.x * TILE;   // Y cols

    // stage sincos of half-angles: 128 samples x 10 wires per side
    for (int idx = tid; idx < TILE * NW; idx += 256) {
        int r = idx / NW;
        int i = idx - r * NW;
        float sx, cx;
        sincosf(0.5f * X[(bm + r) * NW + i], &sx, &cx);
        scx[i][r] = cx;  ssx[i][r] = sx;
        float sy, cy;
        sincosf(0.5f * Y[(bn + r) * NW + i], &sy, &cy);
        scy[i][r] = cy;  ssy[i][r] = sy;
    }
    __syncthreads();

    const int tx = tid & 15;            // y-col group
    const int ty = tid >> 4;            // x-row group
    const int r0 = ty * 8;
    const int c0 = tx * 8;

    float acc[8][8];
#pragma unroll
    for (int r = 0; r < 8; ++r)
#pragma unroll
        for (int c = 0; c < 8; ++c) acc[r][c] = 1.f;

#pragma unroll
    for (int i = 0; i < NW; ++i) {
        float4 cxa = *(const float4*)&scx[i][r0];
        float4 cxb = *(const float4*)&scx[i][r0 + 4];
        float4 sxa = *(const float4*)&ssx[i][r0];
        float4 sxb = *(const float4*)&ssx[i][r0 + 4];
        float4 cya = *(const float4*)&scy[i][c0];
        float4 cyb = *(const float4*)&scy[i][c0 + 4];
        float4 sya = *(const float4*)&ssy[i][c0];
        float4 syb = *(const float4*)&ssy[i][c0 + 4];
        float cx[8] = {cxa.x, cxa.y, cxa.z, cxa.w, cxb.x, cxb.y, cxb.z, cxb.w};
        float sx[8] = {sxa.x, sxa.y, sxa.z, sxa.w, sxb.x, sxb.y, sxb.z, sxb.w};
        float cy[8] = {cya.x, cya.y, cya.z, cya.w, cyb.x, cyb.y, cyb.z, cyb.w};
        float sy[8] = {sya.x, sya.y, sya.z, sya.w, syb.x, syb.y, syb.z, syb.w};
#pragma unroll
        for (int r = 0; r < 8; ++r)
#pragma unroll
            for (int c = 0; c < 8; ++c)
                acc[r][c] *= fmaf(sx[r], sy[c], cx[r] * cy[c]);
    }

    // out = acc^2, vectorized stores
#pragma unroll
    for (int r = 0; r < 8; ++r) {
        float* orow = out + (size_t)(bm + r0 + r) * NSAMP + bn + c0;
#pragma unroll
        for (int c4 = 0; c4 < 2; ++c4) {
            float4 v;
            v.x = acc[r][4 * c4 + 0] * acc[r][4 * c4 + 0];
            v.y = acc[r][4 * c4 + 1] * acc[r][4 * c4 + 1];
            v.z = acc[r][4 * c4 + 2] * acc[r][4 * c4 + 2];
            v.w = acc[r][4 * c4 + 3] * acc[r][4 * c4 + 3];
            *(float4*)(orow + 4 * c4) = v;
        }
    }
}

extern "C" void kernel_launch(void* const* d_in, const int* in_sizes, int n_in,
                              void* d_out, int out_size) {
    const float* X = (const float*)d_in[0];      // (4096, 10)
    const float* Y = (const float*)d_in[1];      // (4096, 10)
    // d_in[2] (params) provably does not affect the output (unitary invariance)
    float* out = (float*)d_out;                  // (4096, 4096)

    dim3 grid(NSAMP / TILE, NSAMP / TILE);       // (32, 32)
    qk_kernel<<<grid, 256>>>(X, Y, out);
}

// round 9
// speedup vs baseline: 97.8519x; 1.1721x over previous
#include <cuda_runtime.h>
#include <math.h>

#define NW 10
#define NSAMP 4096
#define TILE 128

typedef unsigned long long u64;

// out[x, y] = prod_i cos^2((X[x,i] - Y[y,i]) / 2)
// (unitary invariance: shared-params RZ/CNOT circuit cancels in <psi_x|psi_y>;
//  product-state overlap factorizes per qubit:
//  cos((x-y)/2) = cos(x/2)cos(y/2) + sin(x/2)sin(y/2).)

__device__ __forceinline__ u64 pack2(float a, float b) {
    u64 r; asm("mov.b64 %0, {%1, %2};" : "=l"(r) : "f"(a), "f"(b)); return r;
}
__device__ __forceinline__ u64 mul2(u64 a, u64 b) {
    u64 r; asm("mul.rn.f32x2 %0, %1, %2;" : "=l"(r) : "l"(a), "l"(b)); return r;
}
__device__ __forceinline__ u64 fma2(u64 a, u64 b, u64 c) {
    u64 r; asm("fma.rn.f32x2 %0, %1, %2, %3;" : "=l"(r) : "l"(a), "l"(b), "l"(c)); return r;
}

__global__ void __launch_bounds__(256)
qk_kernel(const float* __restrict__ X, const float* __restrict__ Y,
          float* __restrict__ out) {
    // wire-major, 16B-aligned rows
    __shared__ __align__(16) float scx[NW][TILE], ssx[NW][TILE];
    __shared__ __align__(16) float scy[NW][TILE], ssy[NW][TILE];

    const int tid = threadIdx.x;
    const int bm = blockIdx.y * TILE;   // X rows
    const int bn = blockIdx.x * TILE;   // Y cols

    // stage sincos of half-angles: 128 samples x 10 wires per side
    for (int idx = tid; idx < TILE * NW; idx += 256) {
        int r = idx / NW;
        int i = idx - r * NW;
        float sx, cx;
        __sincosf(0.5f * X[(bm + r) * NW + i], &sx, &cx);
        scx[i][r] = cx;  ssx[i][r] = sx;
        float sy, cy;
        __sincosf(0.5f * Y[(bn + r) * NW + i], &sy, &cy);
        scy[i][r] = cy;  ssy[i][r] = sy;
    }
    __syncthreads();

    const int tx = tid & 15;            // y-col group (8 cols = 4 packed pairs)
    const int ty = tid >> 4;            // x-row group (8 rows)
    const int r0 = ty * 8;
    const int c0 = tx * 8;

    const u64 one2 = pack2(1.f, 1.f);
    u64 acc[8][4];
#pragma unroll
    for (int r = 0; r < 8; ++r)
#pragma unroll
        for (int c = 0; c < 4; ++c) acc[r][c] = one2;

#pragma unroll
    for (int i = 0; i < NW; ++i) {
        // y side: read packed pairs directly (f32x2 = two consecutive floats)
        ulonglong2 cyA = *(const ulonglong2*)&scy[i][c0];
        ulonglong2 cyB = *(const ulonglong2*)&scy[i][c0 + 4];
        ulonglong2 syA = *(const ulonglong2*)&ssy[i][c0];
        ulonglong2 syB = *(const ulonglong2*)&ssy[i][c0 + 4];
        u64 cy2[4] = {cyA.x, cyA.y, cyB.x, cyB.y};
        u64 sy2[4] = {syA.x, syA.y, syB.x, syB.y};

        // x side: scalars, broadcast-packed per row
        float4 cxa = *(const float4*)&scx[i][r0];
        float4 cxb = *(const float4*)&scx[i][r0 + 4];
        float4 sxa = *(const float4*)&ssx[i][r0];
        float4 sxb = *(const float4*)&ssx[i][r0 + 4];
        float cxf[8] = {cxa.x, cxa.y, cxa.z, cxa.w, cxb.x, cxb.y, cxb.z, cxb.w};
        float sxf[8] = {sxa.x, sxa.y, sxa.z, sxa.w, sxb.x, sxb.y, sxb.z, sxb.w};

#pragma unroll
        for (int r = 0; r < 8; ++r) {
            u64 cxp = pack2(cxf[r], cxf[r]);
            u64 sxp = pack2(sxf[r], sxf[r]);
#pragma unroll
            for (int c = 0; c < 4; ++c)
                acc[r][c] = mul2(acc[r][c], fma2(sxp, sy2[c], mul2(cxp, cy2[c])));
        }
    }

    // out = acc^2 (packed), 16B stores
#pragma unroll
    for (int r = 0; r < 8; ++r) {
        float* orow = out + (size_t)(bm + r0 + r) * NSAMP + bn + c0;
        ulonglong2 v0, v1;
        v0.x = mul2(acc[r][0], acc[r][0]);
        v0.y = mul2(acc[r][1], acc[r][1]);
        v1.x = mul2(acc[r][2], acc[r][2]);
        v1.y = mul2(acc[r][3], acc[r][3]);
        *(ulonglong2*)(orow)     = v0;
        *(ulonglong2*)(orow + 4) = v1;
    }
}

extern "C" void kernel_launch(void* const* d_in, const int* in_sizes, int n_in,
                              void* d_out, int out_size) {
    const float* X = (const float*)d_in[0];      // (4096, 10)
    const float* Y = (const float*)d_in[1];      // (4096, 10)
    // d_in[2] (params) provably does not affect the output (unitary invariance)
    float* out = (float*)d_out;                  // (4096, 4096)

    dim3 grid(NSAMP / TILE, NSAMP / TILE);       // (32, 32)
    qk_kernel<<<grid, 256>>>(X, Y, out);
}

// round 10
// speedup vs baseline: 133.5175x; 1.3645x over previous
#include <cuda_runtime.h>
#include <math.h>

#define NW 10
#define NP 5                 // wire pairs
#define NSAMP 4096
#define TM 128               // X rows per CTA
#define TN 64                // Y cols per CTA

typedef unsigned long long u64;

// out[x, y] = prod_i cos^2((X[x,i] - Y[y,i]) / 2)
// (unitary invariance: the shared-params RZ/CNOT circuit cancels in <psi_x|psi_y>;
//  the product-state overlap factorizes per qubit.)
// Wire-pair expansion:
//  (ci*cyi + si*syi)(cj*cyj + sj*syj)
//   = (ci*cj)(cyi*cyj) + (ci*sj)(cyi*syj) + (si*cj)(syi*cyj) + (si*sj)(syi*syj)

__device__ __forceinline__ u64 pack2(float a, float b) {
    u64 r; asm("mov.b64 %0, {%1, %2};" : "=l"(r) : "f"(a), "f"(b)); return r;
}
__device__ __forceinline__ u64 mul2(u64 a, u64 b) {
    u64 r; asm("mul.rn.f32x2 %0, %1, %2;" : "=l"(r) : "l"(a), "l"(b)); return r;
}
__device__ __forceinline__ u64 fma2(u64 a, u64 b, u64 c) {
    u64 r; asm("fma.rn.f32x2 %0, %1, %2, %3;" : "=l"(r) : "l"(a), "l"(b), "l"(c)); return r;
}

__global__ void __launch_bounds__(256, 3)
qk_kernel(const float* __restrict__ X, const float* __restrict__ Y,
          float* __restrict__ out) {
    // pair-product tables: q in {cc, cs, sc, ss}
    __shared__ __align__(16) float sxp[NP][4][TM];
    __shared__ __align__(16) float syp[NP][4][TN];

    const int tid = threadIdx.x;
    const int bn = blockIdx.x * TN;     // Y cols
    const int bm = blockIdx.y * TM;     // X rows

    // prologue: 640 x-items + 320 y-items
    for (int it = tid; it < TM * NP + TN * NP; it += 256) {
        if (it < TM * NP) {
            int row = it / NP, p = it - row * NP;
            float si, ci, sj, cj;
            __sincosf(0.5f * X[(bm + row) * NW + 2 * p],     &si, &ci);
            __sincosf(0.5f * X[(bm + row) * NW + 2 * p + 1], &sj, &cj);
            sxp[p][0][row] = ci * cj;
            sxp[p][1][row] = ci * sj;
            sxp[p][2][row] = si * cj;
            sxp[p][3][row] = si * sj;
        } else {
            int jt = it - TM * NP;
            int col = jt / NP, p = jt - col * NP;
            float si, ci, sj, cj;
            __sincosf(0.5f * Y[(bn + col) * NW + 2 * p],     &si, &ci);
            __sincosf(0.5f * Y[(bn + col) * NW + 2 * p + 1], &sj, &cj);
            syp[p][0][col] = ci * cj;
            syp[p][1][col] = ci * sj;
            syp[p][2][col] = si * cj;
            syp[p][3][col] = si * sj;
        }
    }
    __syncthreads();

    const int tx = tid & 15;            // col group: 4 cols = 2 packs
    const int ty = tid >> 4;            // row group: 8 rows
    const int r0 = ty * 8;
    const int c0 = tx * 4;

    u64 acc[8][2];

#pragma unroll
    for (int p = 0; p < NP; ++p) {
        // y side: 4 quantities x 4 cols, natural packed pairs (1 LDS.128 each)
        ulonglong2 ycc = *(const ulonglong2*)&syp[p][0][c0];
        ulonglong2 ycs = *(const ulonglong2*)&syp[p][1][c0];
        ulonglong2 ysc = *(const ulonglong2*)&syp[p][2][c0];
        ulonglong2 yss = *(const ulonglong2*)&syp[p][3][c0];
        u64 y0[4] = {ycc.x, ycs.x, ysc.x, yss.x};
        u64 y1[4] = {ycc.y, ycs.y, ysc.y, yss.y};

        // x side in two half-row blocks to bound register pressure
#pragma unroll
        for (int h = 0; h < 2; ++h) {
            float4 xcc = *(const float4*)&sxp[p][0][r0 + 4 * h];
            float4 xcs = *(const float4*)&sxp[p][1][r0 + 4 * h];
            float4 xsc = *(const float4*)&sxp[p][2][r0 + 4 * h];
            float4 xss = *(const float4*)&sxp[p][3][r0 + 4 * h];
            float fcc[4] = {xcc.x, xcc.y, xcc.z, xcc.w};
            float fcs[4] = {xcs.x, xcs.y, xcs.z, xcs.w};
            float fsc[4] = {xsc.x, xsc.y, xsc.z, xsc.w};
            float fss[4] = {xss.x, xss.y, xss.z, xss.w};
#pragma unroll
            for (int r = 0; r < 4; ++r) {
                u64 ucc = pack2(fcc[r], fcc[r]);
                u64 ucs = pack2(fcs[r], fcs[r]);
                u64 usc = pack2(fsc[r], fsc[r]);
                u64 uss = pack2(fss[r], fss[r]);
                u64 t0 = mul2(ucc, y0[0]);
                t0 = fma2(ucs, y0[1], t0);
                t0 = fma2(usc, y0[2], t0);
                t0 = fma2(uss, y0[3], t0);
                u64 t1 = mul2(ucc, y1[0]);
                t1 = fma2(ucs, y1[1], t1);
                t1 = fma2(usc, y1[2], t1);
                t1 = fma2(uss, y1[3], t1);
                const int rr = 4 * h + r;
                if (p == 0) {
                    acc[rr][0] = t0;
                    acc[rr][1] = t1;
                } else {
                    acc[rr][0] = mul2(acc[rr][0], t0);
                    acc[rr][1] = mul2(acc[rr][1], t1);
                }
            }
        }
    }

    // epilogue: square packed, one 16B store per row
#pragma unroll
    for (int r = 0; r < 8; ++r) {
        ulonglong2 v;
        v.x = mul2(acc[r][0], acc[r][0]);
        v.y = mul2(acc[r][1], acc[r][1]);
        *(ulonglong2*)(out + (size_t)(bm + r0 + r) * NSAMP + bn + c0) = v;
    }
}

extern "C" void kernel_launch(void* const* d_in, const int* in_sizes, int n_in,
                              void* d_out, int out_size) {
    const float* X = (const float*)d_in[0];      // (4096, 10)
    const float* Y = (const float*)d_in[1];      // (4096, 10)
    // d_in[2] (params) provably does not affect the output (unitary invariance)
    float* out = (float*)d_out;                  // (4096, 4096)

    dim3 grid(NSAMP / TN, NSAMP / TM);           // (64, 32)
    qk_kernel<<<grid, 256>>>(X, Y, out);
}